// round 2
// baseline (speedup 1.0000x reference)
#include <cuda_runtime.h>
#include <math.h>

#define BATCH 4
#define SEQ   2048
#define CDIM  1024
#define HD    128
#define QKN   256          // 2*h columns for Q/K projections
#define BQ    32
#define BK    64
#define NQT   (SEQ/BQ)     // 64 q-tiles per batch
#define KPAD  66           // padded row stride for transposed K tile (conflict control)
#define ATT_SMEM ((2*BQ*HD + HD*KPAD + BK*HD + BQ*BK)*4)
#define SCALE_F 0.08838834764831845f   // 128^-0.5

// ---------------- scratch (static device globals: allocation-free) ----------
__device__ __align__(16) float g_Q[BATCH*SEQ*QKN];   // [B*T, 256]  (Q1 | Q2)
__device__ __align__(16) float g_K[BATCH*SEQ*QKN];   // [B*T, 256]  (K1 | K2)
__device__ __align__(16) float g_V[BATCH*SEQ*HD];    // [B*T, 128]
__device__ float g_lambda;

// ---------------- lambda scalar ---------------------------------------------
__global__ void lambda_kernel(const float* __restrict__ lq1, const float* __restrict__ lk1,
                              const float* __restrict__ lq2, const float* __restrict__ lk2) {
  int l = threadIdx.x;
  float a = 0.f, b = 0.f;
  for (int i = l; i < HD; i += 32) { a += lq1[i]*lk1[i]; b += lq2[i]*lk2[i]; }
  #pragma unroll
  for (int off = 16; off; off >>= 1) {
    a += __shfl_xor_sync(0xffffffffu, a, off);
    b += __shfl_xor_sync(0xffffffffu, b, off);
  }
  if (l == 0) g_lambda = expf(a) - expf(b) + 0.8f;
}

// ---------------- fp32 tiled GEMM: C = A[M,K] @ B[K,N] ----------------------
// 64x64 tile, BK=16, 256 threads, 4x4 micro-tile per thread.
__global__ __launch_bounds__(256) void gemm_kernel(const float* __restrict__ A,
                                                   const float* __restrict__ Bm,
                                                   int which, int N, int K) {
  float* C = (which == 0) ? g_Q : (which == 1) ? g_K : g_V;
  __shared__ float Ast[16][65];   // transposed A tile
  __shared__ float Bs[16][64];
  int tid = threadIdx.x;
  int ty = tid >> 4, tx = tid & 15;
  int mBase = blockIdx.y << 6, nBase = blockIdx.x << 6;
  int ar = tid >> 2, ac = (tid & 3) << 2;
  int br = tid >> 4, bc = (tid & 15) << 2;
  float acc[4][4] = {};
  for (int k0 = 0; k0 < K; k0 += 16) {
    float4 av = *(const float4*)(A + (size_t)(mBase + ar)*K + k0 + ac);
    Ast[ac+0][ar] = av.x; Ast[ac+1][ar] = av.y;
    Ast[ac+2][ar] = av.z; Ast[ac+3][ar] = av.w;
    *(float4*)(&Bs[br][bc]) = *(const float4*)(Bm + (size_t)(k0 + br)*N + nBase + bc);
    __syncthreads();
    #pragma unroll
    for (int kk = 0; kk < 16; ++kk) {
      float a0 = Ast[kk][(ty<<2)+0], a1 = Ast[kk][(ty<<2)+1];
      float a2 = Ast[kk][(ty<<2)+2], a3 = Ast[kk][(ty<<2)+3];
      float4 bv = *(const float4*)(&Bs[kk][tx<<2]);
      acc[0][0] += a0*bv.x; acc[0][1] += a0*bv.y; acc[0][2] += a0*bv.z; acc[0][3] += a0*bv.w;
      acc[1][0] += a1*bv.x; acc[1][1] += a1*bv.y; acc[1][2] += a1*bv.z; acc[1][3] += a1*bv.w;
      acc[2][0] += a2*bv.x; acc[2][1] += a2*bv.y; acc[2][2] += a2*bv.z; acc[2][3] += a2*bv.w;
      acc[3][0] += a3*bv.x; acc[3][1] += a3*bv.y; acc[3][2] += a3*bv.z; acc[3][3] += a3*bv.w;
    }
    __syncthreads();
  }
  #pragma unroll
  for (int i = 0; i < 4; ++i) {
    float4 o = make_float4(acc[i][0], acc[i][1], acc[i][2], acc[i][3]);
    *(float4*)(C + (size_t)(mBase + (ty<<2) + i)*N + nBase + (tx<<2)) = o;
  }
}

// ---------------- fused differential flash attention ------------------------
// Block: 256 threads. Handles two q-tiles (x and NQT-1-x) for load balance.
// Thread (ty=tid/32, tx=lane): score tile 4 rows x 2 cols; O tile 4 rows x 4 cols.
__global__ __launch_bounds__(256) void attn_kernel(float* __restrict__ out) {
  extern __shared__ float sm[];
  float* Q1s = sm;                  // [BQ][HD]
  float* Q2s = Q1s + BQ*HD;         // [BQ][HD]
  float* Kst = Q2s + BQ*HD;         // [HD][KPAD] transposed K tile
  float* Vs  = Kst + HD*KPAD;       // [BK][HD]
  float* Ps  = Vs + BK*HD;          // [BQ][BK]

  int b   = blockIdx.y;
  int tid = threadIdx.x;
  int ty  = tid >> 5;               // 0..7  (warp id; warp owns 4 rows)
  int tx  = tid & 31;               // lane
  float lbd = g_lambda;

  for (int half = 0; half < 2; ++half) {
    int qt = half ? (NQT - 1 - (int)blockIdx.x) : (int)blockIdx.x;
    int q0 = qt * BQ;

    __syncthreads();
    // Load Q tile (split into Q1/Q2 halves)
    {
      const float4* qsrc = (const float4*)(g_Q + ((size_t)b*SEQ + q0)*QKN);
      for (int i = tid; i < BQ*64; i += 256) {      // 64 float4 per row
        int r = i >> 6, c4 = i & 63;
        float4 v = qsrc[i];
        float* dst = (c4 < 32) ? (Q1s + r*HD + (c4 << 2))
                               : (Q2s + r*HD + ((c4 - 32) << 2));
        *(float4*)dst = v;
      }
    }

    float O1[4][4] = {}, O2[4][4] = {};
    float m1[4], l1[4], m2[4], l2[4];
    #pragma unroll
    for (int i = 0; i < 4; ++i) { m1[i] = m2[i] = -1e30f; l1[i] = l2[i] = 0.f; }

    int kt_end = min((q0 + BQ) / BK, (SEQ - 1) / BK);
    for (int kt = 0; kt <= kt_end; ++kt) {
      int j0 = kt * BK;
      __syncthreads();   // previous tile's PV done with Vs/Ps
      // Load V tile
      {
        const float4* vsrc = (const float4*)(g_V + ((size_t)b*SEQ + j0)*HD);
        for (int i = tid; i < BK*HD/4; i += 256) ((float4*)Vs)[i] = vsrc[i];
      }

      auto stream = [&](const float* Qsm, int koff,
                        float (&O)[4][4], float (&m)[4], float (&l)[4]) {
        // Load K tile transposed: Kst[d][j]  (scalar, conflict-light with pad 66)
        {
          const float* ksrc = g_K + ((size_t)b*SEQ + j0)*QKN + koff;
          for (int i = tid; i < BK*HD; i += 256) {
            int j = i >> 7, d = i & 127;
            Kst[d*KPAD + j] = ksrc[(size_t)j*QKN + d];
          }
        }
        __syncthreads();  // K (and Q/V on first use) ready; prior Ps readers done

        // Scores: S[4 rows][2 cols], inner dim 128
        float S[4][2] = {};
        const float* qb = Qsm + (ty << 2)*HD;
        #pragma unroll 4
        for (int d = 0; d < HD; d += 4) {
          float qr[4][4];
          #pragma unroll
          for (int r = 0; r < 4; ++r) {
            float4 qv = *(const float4*)(qb + r*HD + d);
            qr[r][0] = qv.x; qr[r][1] = qv.y; qr[r][2] = qv.z; qr[r][3] = qv.w;
          }
          #pragma unroll
          for (int dd = 0; dd < 4; ++dd) {
            float2 kv = *(const float2*)(Kst + (d + dd)*KPAD + (tx << 1));
            #pragma unroll
            for (int r = 0; r < 4; ++r) {
              S[r][0] += qr[r][dd]*kv.x;
              S[r][1] += qr[r][dd]*kv.y;
            }
          }
        }

        // Online softmax update (mask: j <= r+1), write P tile
        int jg = j0 + (tx << 1);
        #pragma unroll
        for (int r = 0; r < 4; ++r) {
          int rg = q0 + (ty << 2) + r;
          float s0 = (jg     <= rg + 1) ? S[r][0]*SCALE_F : -1e30f;
          float s1 = (jg + 1 <= rg + 1) ? S[r][1]*SCALE_F : -1e30f;
          float mx = fmaxf(s0, s1);
          #pragma unroll
          for (int off = 16; off; off >>= 1)
            mx = fmaxf(mx, __shfl_xor_sync(0xffffffffu, mx, off));
          float mnew = fmaxf(m[r], mx);
          float p0 = __expf(s0 - mnew), p1 = __expf(s1 - mnew);
          float rs = p0 + p1;
          #pragma unroll
          for (int off = 16; off; off >>= 1)
            rs += __shfl_xor_sync(0xffffffffu, rs, off);
          float alpha = __expf(m[r] - mnew);
          l[r] = l[r]*alpha + rs;
          m[r] = mnew;
          #pragma unroll
          for (int c = 0; c < 4; ++c) O[r][c] *= alpha;
          *(float2*)(Ps + ((ty << 2) + r)*BK + (tx << 1)) = make_float2(p0, p1);
        }
        __syncthreads();  // Ps ready; all done reading Kst

        // O += P @ V   (4 rows x 4 cols per thread)
        #pragma unroll 4
        for (int kk = 0; kk < BK; ++kk) {
          float4 vv = *(const float4*)(Vs + kk*HD + (tx << 2));
          #pragma unroll
          for (int r = 0; r < 4; ++r) {
            float p = Ps[((ty << 2) + r)*BK + kk];
            O[r][0] += p*vv.x; O[r][1] += p*vv.y;
            O[r][2] += p*vv.z; O[r][3] += p*vv.w;
          }
        }
      };

      stream(Q1s, 0,  O1, m1, l1);
      stream(Q2s, HD, O2, m2, l2);
    }

    // Epilogue: out = O1/l1 - lbd * O2/l2
    float* ob = out + ((size_t)b*SEQ + q0 + (ty << 2))*HD + (tx << 2);
    #pragma unroll
    for (int r = 0; r < 4; ++r) {
      float inv1 = 1.f / l1[r];
      float inv2 = lbd / l2[r];
      float4 o;
      o.x = O1[r][0]*inv1 - O2[r][0]*inv2;
      o.y = O1[r][1]*inv1 - O2[r][1]*inv2;
      o.z = O1[r][2]*inv1 - O2[r][2]*inv2;
      o.w = O1[r][3]*inv1 - O2[r][3]*inv2;
      *(float4*)(ob + (size_t)r*HD) = o;
    }
  }
}

// ---------------- launch -----------------------------------------------------
extern "C" void kernel_launch(void* const* d_in, const int* in_sizes, int n_in,
                              void* d_out, int out_size) {
  const float* q   = (const float*)d_in[0];
  const float* k   = (const float*)d_in[1];
  const float* v   = (const float*)d_in[2];
  const float* Wq  = (const float*)d_in[3];
  const float* Wk  = (const float*)d_in[4];
  const float* Wv  = (const float*)d_in[5];
  const float* lq1 = (const float*)d_in[6];
  const float* lk1 = (const float*)d_in[7];
  const float* lq2 = (const float*)d_in[8];
  const float* lk2 = (const float*)d_in[9];
  float* out = (float*)d_out;

  cudaFuncSetAttribute(attn_kernel, cudaFuncAttributeMaxDynamicSharedMemorySize, ATT_SMEM);

  lambda_kernel<<<1, 32>>>(lq1, lk1, lq2, lk2);

  dim3 gQK(QKN/64, (BATCH*SEQ)/64);   // (4, 512)
  gemm_kernel<<<gQK, 256>>>(q, Wq, 0, QKN, CDIM);
  gemm_kernel<<<gQK, 256>>>(k, Wk, 1, QKN, CDIM);
  dim3 gV(HD/64, (BATCH*SEQ)/64);     // (2, 512)
  gemm_kernel<<<gV, 256>>>(v, Wv, 2, HD, CDIM);

  attn_kernel<<<dim3(NQT/2, BATCH), 256, ATT_SMEM>>>(out);
}

// round 3
// speedup vs baseline: 2.5028x; 2.5028x over previous
#include <cuda_runtime.h>
#include <math.h>
#include <stdint.h>

#define BATCH 4
#define SEQ   2048
#define CDIM  1024
#define HD    128
#define QKN   256
#define SCALE_F 0.08838834764831845f

// attention tiling
#define BQA 32
#define BKA 64
#define NQTA (SEQ/BQA)          // 64 q-tiles per batch
#define KS_STRIDE 132
#define VS_STRIDE 136
#define PS_STRIDE 68
// dynamic smem floats: Ks + Vs + Ps + red
#define ATT_F (BKA*KS_STRIDE + BKA*VS_STRIDE + BQA*PS_STRIDE + 128)
#define ATT_SMEM (ATT_F*4)

// ---------------- scratch ----------------------------------------------------
__device__ __align__(16) float g_Q[BATCH*SEQ*QKN];
__device__ __align__(16) float g_K[BATCH*SEQ*QKN];
__device__ __align__(16) float g_V[BATCH*SEQ*HD];
__device__ float g_lambda;

// ---------------- helpers ----------------------------------------------------
__device__ __forceinline__ uint32_t tf32u(float x) {
  uint32_t y; asm("cvt.rna.tf32.f32 %0, %1;" : "=r"(y) : "f"(x)); return y;
}
__device__ __forceinline__ float tf32f(float x) { return __uint_as_float(tf32u(x)); }

__device__ __forceinline__ void mma8(float& c0, float& c1, float& c2, float& c3,
                                     uint32_t a0, uint32_t a1, uint32_t a2, uint32_t a3,
                                     uint32_t b0, uint32_t b1) {
  asm volatile(
    "mma.sync.aligned.m16n8k8.row.col.f32.tf32.tf32.f32 "
    "{%0,%1,%2,%3}, {%4,%5,%6,%7}, {%8,%9}, {%0,%1,%2,%3};\n"
    : "+f"(c0), "+f"(c1), "+f"(c2), "+f"(c3)
    : "r"(a0), "r"(a1), "r"(a2), "r"(a3), "r"(b0), "r"(b1));
}

// ---------------- lambda ------------------------------------------------------
__global__ void lambda_kernel(const float* __restrict__ lq1, const float* __restrict__ lk1,
                              const float* __restrict__ lq2, const float* __restrict__ lk2) {
  int l = threadIdx.x;
  float a = 0.f, b = 0.f;
  for (int i = l; i < HD; i += 32) { a += lq1[i]*lk1[i]; b += lq2[i]*lk2[i]; }
  #pragma unroll
  for (int off = 16; off; off >>= 1) {
    a += __shfl_xor_sync(0xffffffffu, a, off);
    b += __shfl_xor_sync(0xffffffffu, b, off);
  }
  if (l == 0) g_lambda = expf(a) - expf(b) + 0.8f;
}

// ---------------- tf32 tensor-core projection GEMM ---------------------------
// C[M=8192, N] = A[M,1024] @ W[1024,N]. Block tile 128x64, 8 warps (4m x 2n),
// warp tile 32x32 = 2 m16-tiles x 4 n8-tiles. K chunk 32.
#define AS_STRIDE 36
#define BS_STRIDE 72
__global__ __launch_bounds__(256) void gemm_tc(const float* __restrict__ A,
                                               const float* __restrict__ Bm,
                                               int which, int N) {
  float* C = (which == 0) ? g_Q : (which == 1) ? g_K : g_V;
  __shared__ float As[128*AS_STRIDE];
  __shared__ float Bs[32*BS_STRIDE];
  int tid = threadIdx.x, lane = tid & 31, wid = tid >> 5;
  int wm = wid >> 1, wn = wid & 1;
  int gID = lane >> 2, tig = lane & 3;
  int mBase = blockIdx.y << 7, nBase = blockIdx.x << 6;

  int arow = tid >> 3, acol = (tid & 7) << 2;     // 32 rows/pass, 4 passes
  int brow = tid >> 4, bcol = (tid & 15) << 2;    // 16 rows/pass, 2 passes

  float c[8][4] = {};
  for (int k0 = 0; k0 < CDIM; k0 += 32) {
    __syncthreads();
    #pragma unroll
    for (int p = 0; p < 4; ++p) {
      float4 v = *(const float4*)(A + (size_t)(mBase + arow + 32*p)*CDIM + k0 + acol);
      float* d = As + (arow + 32*p)*AS_STRIDE + acol;
      d[0] = tf32f(v.x); d[1] = tf32f(v.y); d[2] = tf32f(v.z); d[3] = tf32f(v.w);
    }
    #pragma unroll
    for (int p = 0; p < 2; ++p) {
      float4 v = *(const float4*)(Bm + (size_t)(k0 + brow + 16*p)*N + nBase + bcol);
      float* d = Bs + (brow + 16*p)*BS_STRIDE + bcol;
      d[0] = tf32f(v.x); d[1] = tf32f(v.y); d[2] = tf32f(v.z); d[3] = tf32f(v.w);
    }
    __syncthreads();
    #pragma unroll
    for (int ks = 0; ks < 4; ++ks) {
      uint32_t a[2][4], b[4][2];
      #pragma unroll
      for (int mt = 0; mt < 2; ++mt) {
        int r = wm*32 + mt*16 + gID;
        const float* ap = As + r*AS_STRIDE + ks*8;
        a[mt][0] = __float_as_uint(ap[tig]);
        a[mt][1] = __float_as_uint(ap[8*AS_STRIDE + tig]);
        a[mt][2] = __float_as_uint(ap[tig + 4]);
        a[mt][3] = __float_as_uint(ap[8*AS_STRIDE + tig + 4]);
      }
      #pragma unroll
      for (int nt = 0; nt < 4; ++nt) {
        int col = wn*32 + nt*8 + gID;
        b[nt][0] = __float_as_uint(Bs[(ks*8 + tig)*BS_STRIDE + col]);
        b[nt][1] = __float_as_uint(Bs[(ks*8 + tig + 4)*BS_STRIDE + col]);
      }
      #pragma unroll
      for (int mt = 0; mt < 2; ++mt)
        #pragma unroll
        for (int nt = 0; nt < 4; ++nt)
          mma8(c[mt*4+nt][0], c[mt*4+nt][1], c[mt*4+nt][2], c[mt*4+nt][3],
               a[mt][0], a[mt][1], a[mt][2], a[mt][3], b[nt][0], b[nt][1]);
    }
  }
  #pragma unroll
  for (int mt = 0; mt < 2; ++mt)
    #pragma unroll
    for (int nt = 0; nt < 4; ++nt) {
      int r0 = mBase + wm*32 + mt*16 + gID;
      int col = nBase + wn*32 + nt*8 + 2*tig;
      *(float2*)(C + (size_t)r0*N + col)     = make_float2(c[mt*4+nt][0], c[mt*4+nt][1]);
      *(float2*)(C + (size_t)(r0+8)*N + col) = make_float2(c[mt*4+nt][2], c[mt*4+nt][3]);
    }
}

// ---------------- fused differential flash attention (tf32 mma) --------------
// 128 threads = 4 warps. warp: wm=wid&1 -> rows [wm*16, wm*16+16);
// wgrp=wid>>1 -> S cols [wgrp*32,+32), O cols [wgrp*64,+64).
// Two passes (stream1, stream2); stream2 does out -= lbd*O2/l2.
__global__ __launch_bounds__(128) void attn_tc(float* __restrict__ out) {
  extern __shared__ float sm[];
  float* Ks  = sm;                               // [BKA][132]
  float* Vs  = Ks + BKA*KS_STRIDE;               // [BKA][136]
  float* Ps  = Vs + BKA*VS_STRIDE;               // [BQA][68]
  float* red = Ps + BQA*PS_STRIDE;               // [128]

  int bid = blockIdx.x;
  int b, qt;
  if (bid < 148) { b = bid & 3; qt = (NQTA-1) - (bid >> 2); }   // qt 63..27
  else           { int r = bid - 148; b = r & 3; qt = r >> 2; } // qt 0..26
  int q0 = qt * BQA;

  int tid = threadIdx.x, lane = tid & 31, wid = tid >> 5;
  int wm = wid & 1, wgrp = wid >> 1;
  int mrow = wm * 16, scol = wgrp * 32, ocol = wgrp * 64;
  int gID = lane >> 2, tig = lane & 3;
  float lbd = g_lambda;
  int kt_end = min((q0 + BQA) >> 6, (SEQ-1) >> 6);

  for (int pass = 0; pass < 2; ++pass) {
    int koff = pass * HD;
    // Q fragments for this warp's 16 rows (whole 128-dim), kept in regs
    uint32_t qf[16][4];
    {
      const float* qb = g_Q + ((size_t)b*SEQ + q0 + mrow)*QKN + koff;
      #pragma unroll
      for (int ks = 0; ks < 16; ++ks) {
        qf[ks][0] = tf32u(qb[(size_t)gID*QKN     + ks*8 + tig]);
        qf[ks][1] = tf32u(qb[(size_t)(gID+8)*QKN + ks*8 + tig]);
        qf[ks][2] = tf32u(qb[(size_t)gID*QKN     + ks*8 + tig + 4]);
        qf[ks][3] = tf32u(qb[(size_t)(gID+8)*QKN + ks*8 + tig + 4]);
      }
    }

    float O[8][4] = {};
    float m_lo = -1e30f, m_hi = -1e30f, l_lo = 0.f, l_hi = 0.f;

    for (int kt = 0; kt <= kt_end; ++kt) {
      int j0 = kt * BKA;
      __syncthreads();   // prior iter done with Ks/Vs/red
      // stage K,V tiles (tf32-rounded), coalesced float4
      #pragma unroll
      for (int p = 0; p < 16; ++p) {
        int idx = tid + p*128;            // 2048 float4
        int j = idx >> 5, d = (idx & 31) << 2;
        float4 v = *(const float4*)(g_K + ((size_t)b*SEQ + j0 + j)*QKN + koff + d);
        float* dst = Ks + j*KS_STRIDE + d;
        dst[0] = tf32f(v.x); dst[1] = tf32f(v.y); dst[2] = tf32f(v.z); dst[3] = tf32f(v.w);
        float4 w = *(const float4*)(g_V + ((size_t)b*SEQ + j0 + j)*HD + d);
        float* dv = Vs + j*VS_STRIDE + d;
        dv[0] = tf32f(w.x); dv[1] = tf32f(w.y); dv[2] = tf32f(w.z); dv[3] = tf32f(w.w);
      }
      __syncthreads();

      // scores: warp computes its 32 key-cols for its 16 rows
      float S[4][4] = {};
      #pragma unroll
      for (int ks = 0; ks < 16; ++ks) {
        #pragma unroll
        for (int nt = 0; nt < 4; ++nt) {
          int jl = scol + nt*8 + gID;
          uint32_t b0 = __float_as_uint(Ks[jl*KS_STRIDE + ks*8 + tig]);
          uint32_t b1 = __float_as_uint(Ks[jl*KS_STRIDE + ks*8 + tig + 4]);
          mma8(S[nt][0], S[nt][1], S[nt][2], S[nt][3],
               qf[ks][0], qf[ks][1], qf[ks][2], qf[ks][3], b0, b1);
        }
      }

      // mask + scale + row max (quad shfl + cross-warp smem)
      int r_lo = q0 + mrow + gID, r_hi = r_lo + 8;
      float mx0 = -1e30f, mx1 = -1e30f;
      #pragma unroll
      for (int nt = 0; nt < 4; ++nt) {
        int jb = j0 + scol + nt*8 + 2*tig;
        S[nt][0] = (jb     <= r_lo + 1) ? S[nt][0]*SCALE_F : -1e30f;
        S[nt][1] = (jb + 1 <= r_lo + 1) ? S[nt][1]*SCALE_F : -1e30f;
        S[nt][2] = (jb     <= r_hi + 1) ? S[nt][2]*SCALE_F : -1e30f;
        S[nt][3] = (jb + 1 <= r_hi + 1) ? S[nt][3]*SCALE_F : -1e30f;
        mx0 = fmaxf(mx0, fmaxf(S[nt][0], S[nt][1]));
        mx1 = fmaxf(mx1, fmaxf(S[nt][2], S[nt][3]));
      }
      mx0 = fmaxf(mx0, __shfl_xor_sync(0xffffffffu, mx0, 1));
      mx0 = fmaxf(mx0, __shfl_xor_sync(0xffffffffu, mx0, 2));
      mx1 = fmaxf(mx1, __shfl_xor_sync(0xffffffffu, mx1, 1));
      mx1 = fmaxf(mx1, __shfl_xor_sync(0xffffffffu, mx1, 2));
      if (tig == 0) {
        red[wgrp*32 + mrow + gID]     = mx0;
        red[wgrp*32 + mrow + gID + 8] = mx1;
      }
      __syncthreads();
      mx0 = fmaxf(mx0, red[(wgrp^1)*32 + mrow + gID]);
      mx1 = fmaxf(mx1, red[(wgrp^1)*32 + mrow + gID + 8]);
      float mn0 = fmaxf(m_lo, mx0), mn1 = fmaxf(m_hi, mx1);
      float al0 = __expf(m_lo - mn0), al1 = __expf(m_hi - mn1);
      m_lo = mn0; m_hi = mn1;

      // p = exp(s - m), write P (tf32), partial row sums
      float s0 = 0.f, s1 = 0.f;
      #pragma unroll
      for (int nt = 0; nt < 4; ++nt) {
        float p00 = __expf(S[nt][0] - mn0), p01 = __expf(S[nt][1] - mn0);
        float p10 = __expf(S[nt][2] - mn1), p11 = __expf(S[nt][3] - mn1);
        s0 += p00 + p01; s1 += p10 + p11;
        int cl = scol + nt*8 + 2*tig;
        *(float2*)(Ps + (mrow + gID)*PS_STRIDE + cl)     = make_float2(tf32f(p00), tf32f(p01));
        *(float2*)(Ps + (mrow + gID + 8)*PS_STRIDE + cl) = make_float2(tf32f(p10), tf32f(p11));
      }
      s0 += __shfl_xor_sync(0xffffffffu, s0, 1); s0 += __shfl_xor_sync(0xffffffffu, s0, 2);
      s1 += __shfl_xor_sync(0xffffffffu, s1, 1); s1 += __shfl_xor_sync(0xffffffffu, s1, 2);
      if (tig == 0) {
        red[64 + wgrp*32 + mrow + gID]     = s0;
        red[64 + wgrp*32 + mrow + gID + 8] = s1;
      }
      __syncthreads();  // Ps + row sums visible
      s0 += red[64 + (wgrp^1)*32 + mrow + gID];
      s1 += red[64 + (wgrp^1)*32 + mrow + gID + 8];
      l_lo = l_lo*al0 + s0;
      l_hi = l_hi*al1 + s1;
      #pragma unroll
      for (int nt = 0; nt < 8; ++nt) {
        O[nt][0] *= al0; O[nt][1] *= al0; O[nt][2] *= al1; O[nt][3] *= al1;
      }

      // O += P @ V  (warp covers its 64 O-cols, full BKA=64 k)
      #pragma unroll
      for (int kk = 0; kk < 8; ++kk) {
        const float* pr0 = Ps + (mrow + gID)*PS_STRIDE + kk*8;
        const float* pr1 = Ps + (mrow + gID + 8)*PS_STRIDE + kk*8;
        uint32_t pa0 = __float_as_uint(pr0[tig]);
        uint32_t pa1 = __float_as_uint(pr1[tig]);
        uint32_t pa2 = __float_as_uint(pr0[tig + 4]);
        uint32_t pa3 = __float_as_uint(pr1[tig + 4]);
        #pragma unroll
        for (int nt = 0; nt < 8; ++nt) {
          int col = ocol + nt*8 + gID;
          uint32_t b0 = __float_as_uint(Vs[(kk*8 + tig)*VS_STRIDE + col]);
          uint32_t b1 = __float_as_uint(Vs[(kk*8 + tig + 4)*VS_STRIDE + col]);
          mma8(O[nt][0], O[nt][1], O[nt][2], O[nt][3], pa0, pa1, pa2, pa3, b0, b1);
        }
      }
    } // kt

    // epilogue
    float il0 = 1.f / l_lo, il1 = 1.f / l_hi;
    float* ob = out + ((size_t)b*SEQ + q0 + mrow)*HD;
    #pragma unroll
    for (int nt = 0; nt < 8; ++nt) {
      int col = ocol + nt*8 + 2*tig;
      float2* p0 = (float2*)(ob + (size_t)gID*HD + col);
      float2* p1 = (float2*)(ob + (size_t)(gID+8)*HD + col);
      if (pass == 0) {
        *p0 = make_float2(O[nt][0]*il0, O[nt][1]*il0);
        *p1 = make_float2(O[nt][2]*il1, O[nt][3]*il1);
      } else {
        float2 a = *p0, c2 = *p1;
        a.x  -= lbd*O[nt][0]*il0; a.y  -= lbd*O[nt][1]*il0;
        c2.x -= lbd*O[nt][2]*il1; c2.y -= lbd*O[nt][3]*il1;
        *p0 = a; *p1 = c2;
      }
    }
  } // pass
}

// ---------------- launch ------------------------------------------------------
extern "C" void kernel_launch(void* const* d_in, const int* in_sizes, int n_in,
                              void* d_out, int out_size) {
  const float* q   = (const float*)d_in[0];
  const float* k   = (const float*)d_in[1];
  const float* v   = (const float*)d_in[2];
  const float* Wq  = (const float*)d_in[3];
  const float* Wk  = (const float*)d_in[4];
  const float* Wv  = (const float*)d_in[5];
  const float* lq1 = (const float*)d_in[6];
  const float* lk1 = (const float*)d_in[7];
  const float* lq2 = (const float*)d_in[8];
  const float* lk2 = (const float*)d_in[9];
  float* out = (float*)d_out;

  cudaFuncSetAttribute(attn_tc, cudaFuncAttributeMaxDynamicSharedMemorySize, ATT_SMEM);

  lambda_kernel<<<1, 32>>>(lq1, lk1, lq2, lk2);

  dim3 gQK(QKN/64, (BATCH*SEQ)/128);   // (4, 64)
  gemm_tc<<<gQK, 256>>>(q, Wq, 0, QKN);
  gemm_tc<<<gQK, 256>>>(k, Wk, 1, QKN);
  dim3 gV(HD/64, (BATCH*SEQ)/128);     // (2, 64)
  gemm_tc<<<gV, 256>>>(v, Wv, 2, HD);

  attn_tc<<<4*NQTA, 128, ATT_SMEM>>>(out);
}

// round 5
// speedup vs baseline: 3.8209x; 1.5267x over previous
#include <cuda_runtime.h>
#include <math.h>
#include <stdint.h>

#define BATCH 4
#define SEQ   2048
#define CDIM  1024
#define HD    128
#define QKN   256
#define SCALE_F 0.08838834764831845f

// attention tiling
#define BQA 32
#define BKA 64
#define NQTA (SEQ/BQA)          // 64 q-tiles per batch
#define KSS 132                 // K smem stride (=4 mod 32: conflict-free B-col frag reads)
#define VSS 136                 // V smem stride (=8 mod 32)
#define PSS 68
#define KS_TILE (BKA*KSS)       // 8448 floats per (db,stream) K tile
#define ATT_F (4*KS_TILE + BKA*VSS + 2*BQA*PSS + 256)
#define ATT_SMEM (ATT_F*4)      // ~184 KB

// ---------------- scratch ----------------------------------------------------
__device__ __align__(16) float g_Q[BATCH*SEQ*QKN];   // pre-scaled, tf32-rounded
__device__ __align__(16) float g_K[BATCH*SEQ*QKN];   // tf32-rounded
__device__ __align__(16) float g_V[BATCH*SEQ*HD];    // tf32-rounded
__device__ float g_lambda;

// ---------------- helpers ----------------------------------------------------
__device__ __forceinline__ uint32_t tf32u(float x) {
  uint32_t y; asm("cvt.rna.tf32.f32 %0, %1;" : "=r"(y) : "f"(x)); return y;
}
__device__ __forceinline__ float tf32f(float x) { return __uint_as_float(tf32u(x)); }

__device__ __forceinline__ void mma8(float& c0, float& c1, float& c2, float& c3,
                                     uint32_t a0, uint32_t a1, uint32_t a2, uint32_t a3,
                                     uint32_t b0, uint32_t b1) {
  asm volatile(
    "mma.sync.aligned.m16n8k8.row.col.f32.tf32.tf32.f32 "
    "{%0,%1,%2,%3}, {%4,%5,%6,%7}, {%8,%9}, {%0,%1,%2,%3};\n"
    : "+f"(c0), "+f"(c1), "+f"(c2), "+f"(c3)
    : "r"(a0), "r"(a1), "r"(a2), "r"(a3), "r"(b0), "r"(b1));
}

__device__ __forceinline__ void cpa16(uint32_t dst, const void* src) {
  asm volatile("cp.async.cg.shared.global [%0], [%1], 16;" :: "r"(dst), "l"(src));
}
#define CP_COMMIT() asm volatile("cp.async.commit_group;" ::: "memory")

// ---------------- lambda ------------------------------------------------------
__global__ void lambda_kernel(const float* __restrict__ lq1, const float* __restrict__ lk1,
                              const float* __restrict__ lq2, const float* __restrict__ lk2) {
  int l = threadIdx.x;
  float a = 0.f, b = 0.f;
  for (int i = l; i < HD; i += 32) { a += lq1[i]*lk1[i]; b += lq2[i]*lk2[i]; }
  #pragma unroll
  for (int off = 16; off; off >>= 1) {
    a += __shfl_xor_sync(0xffffffffu, a, off);
    b += __shfl_xor_sync(0xffffffffu, b, off);
  }
  if (l == 0) g_lambda = expf(a) - expf(b) + 0.8f;
}

// ---------------- fused tf32 projection GEMMs (all 3 in one launch) ----------
// 64x64 tile, 128 threads (4 warps 2x2, warp 32x32), Kc=32, double-buffered.
#define AST 36   // =4 mod 32
#define BST 72   // =8 mod 32
__global__ __launch_bounds__(128) void gemm_all(
    const float* __restrict__ q, const float* __restrict__ k, const float* __restrict__ v,
    const float* __restrict__ Wq, const float* __restrict__ Wk, const float* __restrict__ Wv) {
  __shared__ float As[2][64*AST];
  __shared__ float Bs[2][32*BST];

  int bid = blockIdx.x;
  const float *A, *Bm; float* C; int N, mBase, nBase; float scale = 1.f;
  if (bid < 512)       { A=q; Bm=Wq; C=g_Q; N=QKN; mBase=(bid>>2)<<6;        nBase=(bid&3)<<6; scale=SCALE_F; }
  else if (bid < 1024) { int l=bid-512;  A=k; Bm=Wk; C=g_K; N=QKN; mBase=(l>>2)<<6; nBase=(l&3)<<6; }
  else                 { int l=bid-1024; A=v; Bm=Wv; C=g_V; N=HD;  mBase=(l>>1)<<6; nBase=(l&1)<<6; }

  int tid = threadIdx.x, lane = tid & 31, wid = tid >> 5;
  int wm = wid & 1, wn = wid >> 1;
  int gID = lane >> 2, tig = lane & 3;
  int arow = tid >> 3, acol = (tid & 7) << 2;    // A: 16 rows/pass x4
  int brow = tid >> 4, bcol = (tid & 15) << 2;   // B: 8 rows/pass x4

  float4 ra[4], rb[4];
  auto ldt = [&](int it) {
    int k0 = it << 5;
    #pragma unroll
    for (int p = 0; p < 4; ++p)
      ra[p] = *(const float4*)(A + (size_t)(mBase + arow + 16*p)*CDIM + k0 + acol);
    #pragma unroll
    for (int p = 0; p < 4; ++p)
      rb[p] = *(const float4*)(Bm + (size_t)(k0 + brow + 8*p)*N + nBase + bcol);
  };
  auto stt = [&](int buf) {
    #pragma unroll
    for (int p = 0; p < 4; ++p) {
      float* d = As[buf] + (arow + 16*p)*AST + acol;
      d[0]=tf32f(ra[p].x); d[1]=tf32f(ra[p].y); d[2]=tf32f(ra[p].z); d[3]=tf32f(ra[p].w);
    }
    #pragma unroll
    for (int p = 0; p < 4; ++p) {
      float* d = Bs[buf] + (brow + 8*p)*BST + bcol;
      d[0]=tf32f(rb[p].x); d[1]=tf32f(rb[p].y); d[2]=tf32f(rb[p].z); d[3]=tf32f(rb[p].w);
    }
  };

  float c[8][4] = {};
  ldt(0); stt(0); __syncthreads();
  for (int it = 0; it < 32; ++it) {
    int cb = it & 1;
    if (it < 31) ldt(it + 1);
    #pragma unroll
    for (int ks = 0; ks < 4; ++ks) {
      uint32_t a[2][4], bf[4][2];
      #pragma unroll
      for (int mt = 0; mt < 2; ++mt) {
        const float* ap = As[cb] + (wm*32 + mt*16 + gID)*AST + ks*8;
        a[mt][0] = __float_as_uint(ap[tig]);
        a[mt][1] = __float_as_uint(ap[8*AST + tig]);
        a[mt][2] = __float_as_uint(ap[tig + 4]);
        a[mt][3] = __float_as_uint(ap[8*AST + tig + 4]);
      }
      #pragma unroll
      for (int nt = 0; nt < 4; ++nt) {
        int col = wn*32 + nt*8 + gID;
        bf[nt][0] = __float_as_uint(Bs[cb][(ks*8 + tig)*BST + col]);
        bf[nt][1] = __float_as_uint(Bs[cb][(ks*8 + tig + 4)*BST + col]);
      }
      #pragma unroll
      for (int mt = 0; mt < 2; ++mt)
        #pragma unroll
        for (int nt = 0; nt < 4; ++nt)
          mma8(c[mt*4+nt][0], c[mt*4+nt][1], c[mt*4+nt][2], c[mt*4+nt][3],
               a[mt][0], a[mt][1], a[mt][2], a[mt][3], bf[nt][0], bf[nt][1]);
    }
    if (it < 31) { stt(cb ^ 1); __syncthreads(); }
  }
  #pragma unroll
  for (int mt = 0; mt < 2; ++mt)
    #pragma unroll
    for (int nt = 0; nt < 4; ++nt) {
      int r0 = mBase + wm*32 + mt*16 + gID;
      int col = nBase + wn*32 + nt*8 + 2*tig;
      float* f = c[mt*4+nt];
      *(float2*)(C + (size_t)r0*N + col)     = make_float2(tf32f(f[0]*scale), tf32f(f[1]*scale));
      *(float2*)(C + (size_t)(r0+8)*N + col) = make_float2(tf32f(f[2]*scale), tf32f(f[3]*scale));
    }
}

// ---------------- fused differential flash attention (merged streams) --------
// 256 threads = 8 warps: stream=wid&1 (4 warps/stream), within stream:
// wm=(wid>>1)&1 -> rows [wm*16,+16), wgrp=wid>>2 -> S cols [wgrp*32,+32),
// O cols [wgrp*64,+64). K double-buffered via cp.async; V single-buffer
// (load overlapped with score phase). Single out write (stream1 combines via smem).
__global__ __launch_bounds__(256, 1) void attn_tc(float* __restrict__ out) {
  extern __shared__ float sm[];
  float* Ks  = sm;                        // [db][stream][64][KSS]
  float* Vs  = Ks + 4*KS_TILE;            // [64][VSS]
  float* Ps  = Vs + BKA*VSS;              // [stream][32][PSS]
  float* red = Ps + 2*BQA*PSS;            // [stream][128]

  int bid = blockIdx.x;
  int b, qt;
  if (bid < 148) { b = bid & 3; qt = (NQTA-1) - (bid >> 2); }
  else           { int r = bid - 148; b = r & 3; qt = r >> 2; }
  int q0 = qt * BQA;

  int tid = threadIdx.x, lane = tid & 31, wid = tid >> 5;
  int stream = wid & 1, wsub = wid >> 1;
  int wm = wsub & 1, wgrp = wsub >> 1;
  int mrow = wm*16, scol = wgrp*32, ocol = wgrp*64;
  int gID = lane >> 2, tig = lane & 3;
  float lbd = g_lambda;
  int kt_end = min((q0 + BQA) >> 6, (SEQ-1) >> 6);

  uint32_t KsU = (uint32_t)__cvta_generic_to_shared(Ks);
  uint32_t VsU = (uint32_t)__cvta_generic_to_shared(Vs);

  auto issueK = [&](int ktile, int dbuf) {
    int j0 = ktile * BKA;
    #pragma unroll
    for (int i = 0; i < 16; ++i) {
      int idx = tid + i*256;           // 0..4095
      int st  = idx >> 11;
      int rem = idx & 2047;
      int j = rem >> 5, d4 = rem & 31;
      const float* src = g_K + ((size_t)(b*SEQ + j0 + j))*QKN + st*HD + (d4 << 2);
      uint32_t dst = KsU + (((dbuf*2 + st)*KS_TILE) + j*KSS + (d4 << 2))*4u;
      cpa16(dst, src);
    }
  };
  auto issueV = [&](int ktile) {
    int j0 = ktile * BKA;
    #pragma unroll
    for (int i = 0; i < 8; ++i) {
      int idx = tid + i*256;           // 0..2047
      int j = idx >> 5, d4 = idx & 31;
      const float* src = g_V + ((size_t)(b*SEQ + j0 + j))*HD + (d4 << 2);
      uint32_t dst = VsU + (j*VSS + (d4 << 2))*4u;
      cpa16(dst, src);
    }
  };

  // Q fragments for this warp's 16 rows, its stream's 128-dim, kept in regs.
  uint32_t qf[16][4];
  {
    const float* qb = g_Q + ((size_t)(b*SEQ + q0 + mrow))*QKN + stream*HD;
    #pragma unroll
    for (int ks = 0; ks < 16; ++ks) {
      qf[ks][0] = __float_as_uint(qb[(size_t)gID*QKN     + ks*8 + tig]);
      qf[ks][1] = __float_as_uint(qb[(size_t)(gID+8)*QKN + ks*8 + tig]);
      qf[ks][2] = __float_as_uint(qb[(size_t)gID*QKN     + ks*8 + tig + 4]);
      qf[ks][3] = __float_as_uint(qb[(size_t)(gID+8)*QKN + ks*8 + tig + 4]);
    }
  }

  float O[8][4] = {};
  float m_lo = -1e30f, m_hi = -1e30f, l_lo = 0.f, l_hi = 0.f;

  issueK(0, 0); CP_COMMIT();

  for (int kt = 0; kt <= kt_end; ++kt) {
    int db = kt & 1;
    __syncthreads();                 // prev PV done: Vs/Ps free; Kbuf[db^1] readers done
    issueV(kt); CP_COMMIT();
    bool more = (kt < kt_end);
    if (more) { issueK(kt + 1, db ^ 1); CP_COMMIT(); }
    if (more) asm volatile("cp.async.wait_group 1;" ::: "memory");
    else      asm volatile("cp.async.wait_group 0;" ::: "memory");
    __syncthreads();                 // K(kt)+V(kt) visible

    // scores (Q pre-scaled, so S is already s*SCALE)
    const float* Kb = Ks + (db*2 + stream)*KS_TILE;
    float S[4][4] = {};
    #pragma unroll
    for (int ks = 0; ks < 16; ++ks) {
      #pragma unroll
      for (int nt = 0; nt < 4; ++nt) {
        int jl = scol + nt*8 + gID;
        uint32_t b0 = __float_as_uint(Kb[jl*KSS + ks*8 + tig]);
        uint32_t b1 = __float_as_uint(Kb[jl*KSS + ks*8 + tig + 4]);
        mma8(S[nt][0], S[nt][1], S[nt][2], S[nt][3],
             qf[ks][0], qf[ks][1], qf[ks][2], qf[ks][3], b0, b1);
      }
    }

    // mask + row max
    int j0k = kt * BKA;
    int r_lo = q0 + mrow + gID, r_hi = r_lo + 8;
    float mx0 = -1e30f, mx1 = -1e30f;
    #pragma unroll
    for (int nt = 0; nt < 4; ++nt) {
      int jb = j0k + scol + nt*8 + 2*tig;
      S[nt][0] = (jb     <= r_lo + 1) ? S[nt][0] : -1e30f;
      S[nt][1] = (jb + 1 <= r_lo + 1) ? S[nt][1] : -1e30f;
      S[nt][2] = (jb     <= r_hi + 1) ? S[nt][2] : -1e30f;
      S[nt][3] = (jb + 1 <= r_hi + 1) ? S[nt][3] : -1e30f;
      mx0 = fmaxf(mx0, fmaxf(S[nt][0], S[nt][1]));
      mx1 = fmaxf(mx1, fmaxf(S[nt][2], S[nt][3]));
    }
    mx0 = fmaxf(mx0, __shfl_xor_sync(0xffffffffu, mx0, 1));
    mx0 = fmaxf(mx0, __shfl_xor_sync(0xffffffffu, mx0, 2));
    mx1 = fmaxf(mx1, __shfl_xor_sync(0xffffffffu, mx1, 1));
    mx1 = fmaxf(mx1, __shfl_xor_sync(0xffffffffu, mx1, 2));
    float* redS = red + stream*128;
    if (tig == 0) {
      redS[wgrp*32 + mrow + gID]     = mx0;
      redS[wgrp*32 + mrow + gID + 8] = mx1;
    }
    __syncthreads();
    mx0 = fmaxf(mx0, redS[(wgrp^1)*32 + mrow + gID]);
    mx1 = fmaxf(mx1, redS[(wgrp^1)*32 + mrow + gID + 8]);
    float mn0 = fmaxf(m_lo, mx0), mn1 = fmaxf(m_hi, mx1);
    float al0 = __expf(m_lo - mn0), al1 = __expf(m_hi - mn1);
    m_lo = mn0; m_hi = mn1;

    // p = exp(s-m), write P (tf32), partial row sums
    float* PsS = Ps + stream*BQA*PSS;
    float s0 = 0.f, s1 = 0.f;
    #pragma unroll
    for (int nt = 0; nt < 4; ++nt) {
      float p00 = __expf(S[nt][0] - mn0), p01 = __expf(S[nt][1] - mn0);
      float p10 = __expf(S[nt][2] - mn1), p11 = __expf(S[nt][3] - mn1);
      s0 += p00 + p01; s1 += p10 + p11;
      int cl = scol + nt*8 + 2*tig;
      *(float2*)(PsS + (mrow + gID)*PSS + cl)     = make_float2(tf32f(p00), tf32f(p01));
      *(float2*)(PsS + (mrow + gID + 8)*PSS + cl) = make_float2(tf32f(p10), tf32f(p11));
    }
    s0 += __shfl_xor_sync(0xffffffffu, s0, 1); s0 += __shfl_xor_sync(0xffffffffu, s0, 2);
    s1 += __shfl_xor_sync(0xffffffffu, s1, 1); s1 += __shfl_xor_sync(0xffffffffu, s1, 2);
    if (tig == 0) {
      redS[64 + wgrp*32 + mrow + gID]     = s0;
      redS[64 + wgrp*32 + mrow + gID + 8] = s1;
    }
    __syncthreads();                 // Ps + sums visible
    s0 += redS[64 + (wgrp^1)*32 + mrow + gID];
    s1 += redS[64 + (wgrp^1)*32 + mrow + gID + 8];
    l_lo = l_lo*al0 + s0;
    l_hi = l_hi*al1 + s1;
    #pragma unroll
    for (int nt = 0; nt < 8; ++nt) {
      O[nt][0] *= al0; O[nt][1] *= al0; O[nt][2] *= al1; O[nt][3] *= al1;
    }

    // O += P @ V
    #pragma unroll
    for (int kk = 0; kk < 8; ++kk) {
      const float* pr0 = PsS + (mrow + gID)*PSS + kk*8;
      const float* pr1 = PsS + (mrow + gID + 8)*PSS + kk*8;
      uint32_t pa0 = __float_as_uint(pr0[tig]);
      uint32_t pa1 = __float_as_uint(pr1[tig]);
      uint32_t pa2 = __float_as_uint(pr0[tig + 4]);
      uint32_t pa3 = __float_as_uint(pr1[tig + 4]);
      #pragma unroll
      for (int nt = 0; nt < 8; ++nt) {
        int col = ocol + nt*8 + gID;
        uint32_t b0 = __float_as_uint(Vs[(kk*8 + tig)*VSS + col]);
        uint32_t b1 = __float_as_uint(Vs[(kk*8 + tig + 4)*VSS + col]);
        mma8(O[nt][0], O[nt][1], O[nt][2], O[nt][3], pa0, pa1, pa2, pa3, b0, b1);
      }
    }
  } // kt

  // combine streams: stream1 writes lbd*O2/l2 to smem; stream0 subtracts & stores.
  float il0 = 1.f / l_lo, il1 = 1.f / l_hi;
  __syncthreads();                   // all PV done; Ps area reusable
  if (stream == 1) {
    #pragma unroll
    for (int nt = 0; nt < 8; ++nt) {
      int col = ocol + nt*8 + 2*tig;
      *(float2*)(Ps + (mrow + gID)*132 + col) =
          make_float2(lbd*O[nt][0]*il0, lbd*O[nt][1]*il0);
      *(float2*)(Ps + (mrow + gID + 8)*132 + col) =
          make_float2(lbd*O[nt][2]*il1, lbd*O[nt][3]*il1);
    }
  }
  __syncthreads();
  if (stream == 0) {
    float* ob = out + ((size_t)(b*SEQ + q0 + mrow))*HD;
    #pragma unroll
    for (int nt = 0; nt < 8; ++nt) {
      int col = ocol + nt*8 + 2*tig;
      float2 c0 = *(float2*)(Ps + (mrow + gID)*132 + col);
      float2 c1 = *(float2*)(Ps + (mrow + gID + 8)*132 + col);
      *(float2*)(ob + (size_t)gID*HD + col) =
          make_float2(O[nt][0]*il0 - c0.x, O[nt][1]*il0 - c0.y);
      *(float2*)(ob + (size_t)(gID+8)*HD + col) =
          make_float2(O[nt][2]*il1 - c1.x, O[nt][3]*il1 - c1.y);
    }
  }
}

// ---------------- launch ------------------------------------------------------
extern "C" void kernel_launch(void* const* d_in, const int* in_sizes, int n_in,
                              void* d_out, int out_size) {
  const float* q   = (const float*)d_in[0];
  const float* k   = (const float*)d_in[1];
  const float* v   = (const float*)d_in[2];
  const float* Wq  = (const float*)d_in[3];
  const float* Wk  = (const float*)d_in[4];
  const float* Wv  = (const float*)d_in[5];
  const float* lq1 = (const float*)d_in[6];
  const float* lk1 = (const float*)d_in[7];
  const float* lq2 = (const float*)d_in[8];
  const float* lk2 = (const float*)d_in[9];
  float* out = (float*)d_out;

  cudaFuncSetAttribute(attn_tc, cudaFuncAttributeMaxDynamicSharedMemorySize, ATT_SMEM);

  lambda_kernel<<<1, 32>>>(lq1, lk1, lq2, lk2);
  gemm_all<<<1280, 128>>>(q, k, v, Wq, Wk, Wv);
  attn_tc<<<4*NQTA, 256, ATT_SMEM>>>(out);
}

// round 7
// speedup vs baseline: 3.8840x; 1.0165x over previous
#include <cuda_runtime.h>
#include <math.h>
#include <stdint.h>

#define BATCH 4
#define SEQ   2048
#define CDIM  1024
#define HD    128
#define QKN   256
#define SCALE_F 0.08838834764831845f

// attention tiling
#define BQA 32
#define BKA 64
#define NQTA (SEQ/BQA)
#define KSS 132                  // K smem stride
#define VSS 136                  // V smem stride
#define PSW 36                   // per-warp P stride
#define OBS 132                  // O combine buffer stride
#define KS_TILE (BKA*KSS)        // 8448
#define PS_OFF (4*KS_TILE + BKA*VSS)        // 33792 + 8704
#define ML_OFF (PS_OFF + 8*16*PSW)          // + 4608
#define ATT_F  (ML_OFF + 384)
#define ATT_SMEM (ATT_F*4)       // ~185.5 KB

// gemm smem (dynamic): As 2*64*36 + Bs 2*32*136 floats
#define GAST 36
#define GBST 136
#define GEMM_AF (2*64*GAST)
#define GEMM_F  (GEMM_AF + 2*32*GBST)
#define GEMM_SMEM (GEMM_F*4)     // 53248 B

// ---------------- scratch ----------------------------------------------------
__device__ __align__(16) float g_Q[BATCH*SEQ*QKN];   // pre-scaled, tf32-rounded
__device__ __align__(16) float g_K[BATCH*SEQ*QKN];   // tf32-rounded
__device__ __align__(16) float g_V[BATCH*SEQ*HD];    // tf32-rounded

// ---------------- helpers ----------------------------------------------------
__device__ __forceinline__ uint32_t tf32u(float x) {
  uint32_t y; asm("cvt.rna.tf32.f32 %0, %1;" : "=r"(y) : "f"(x)); return y;
}
__device__ __forceinline__ float tf32f(float x) { return __uint_as_float(tf32u(x)); }

__device__ __forceinline__ void mma8(float& c0, float& c1, float& c2, float& c3,
                                     uint32_t a0, uint32_t a1, uint32_t a2, uint32_t a3,
                                     uint32_t b0, uint32_t b1) {
  asm volatile(
    "mma.sync.aligned.m16n8k8.row.col.f32.tf32.tf32.f32 "
    "{%0,%1,%2,%3}, {%4,%5,%6,%7}, {%8,%9}, {%0,%1,%2,%3};\n"
    : "+f"(c0), "+f"(c1), "+f"(c2), "+f"(c3)
    : "r"(a0), "r"(a1), "r"(a2), "r"(a3), "r"(b0), "r"(b1));
}

__device__ __forceinline__ void cpa16(uint32_t dst, const void* src) {
  asm volatile("cp.async.cg.shared.global [%0], [%1], 16;" :: "r"(dst), "l"(src));
}
#define CP_COMMIT() asm volatile("cp.async.commit_group;" ::: "memory")

// ---------------- fused tf32 projection GEMMs (64x128 tiles) -----------------
// 128 threads, 4 warps (2m x 2n), warp tile 32x64, Kc=32, double-buffered.
__global__ __launch_bounds__(128) void gemm_all(
    const float* __restrict__ q, const float* __restrict__ k, const float* __restrict__ v,
    const float* __restrict__ Wq, const float* __restrict__ Wk, const float* __restrict__ Wv) {
  extern __shared__ float gsm[];
  float* Asm = gsm;                       // [2][64*GAST]
  float* Bsm = gsm + GEMM_AF;             // [2][32*GBST]

  int bid = blockIdx.x;
  const float *A, *Bm; float* C; int N, mBase, nBase; float scale = 1.f;
  if (bid < 256)      { A=q; Bm=Wq; C=g_Q; N=QKN; mBase=(bid>>1)<<6;        nBase=(bid&1)<<7; scale=SCALE_F; }
  else if (bid < 512) { int l=bid-256; A=k; Bm=Wk; C=g_K; N=QKN; mBase=(l>>1)<<6; nBase=(l&1)<<7; }
  else                { int l=bid-512; A=v; Bm=Wv; C=g_V; N=HD;  mBase=l<<6;      nBase=0; }

  int tid = threadIdx.x, lane = tid & 31, wid = tid >> 5;
  int wm = wid >> 1, wn = wid & 1;
  int gID = lane >> 2, tig = lane & 3;
  int arow = tid >> 3, acol = (tid & 7) << 2;     // 16 rows/pass x4
  int brow = tid >> 5, bcol = (tid & 31) << 2;    // 4 rows/pass x8

  float4 ra[4], rb[8];
  auto ldt = [&](int it) {
    int k0 = it << 5;
    #pragma unroll
    for (int p = 0; p < 4; ++p)
      ra[p] = *(const float4*)(A + (size_t)(mBase + arow + 16*p)*CDIM + k0 + acol);
    #pragma unroll
    for (int p = 0; p < 8; ++p)
      rb[p] = *(const float4*)(Bm + (size_t)(k0 + brow + 4*p)*N + nBase + bcol);
  };
  auto stt = [&](int buf) {
    float* Ab = Asm + buf*(64*GAST);
    float* Bb = Bsm + buf*(32*GBST);
    #pragma unroll
    for (int p = 0; p < 4; ++p) {
      float* d = Ab + (arow + 16*p)*GAST + acol;
      d[0]=tf32f(ra[p].x); d[1]=tf32f(ra[p].y); d[2]=tf32f(ra[p].z); d[3]=tf32f(ra[p].w);
    }
    #pragma unroll
    for (int p = 0; p < 8; ++p) {
      float* d = Bb + (brow + 4*p)*GBST + bcol;
      d[0]=tf32f(rb[p].x); d[1]=tf32f(rb[p].y); d[2]=tf32f(rb[p].z); d[3]=tf32f(rb[p].w);
    }
  };

  float c[16][4] = {};
  ldt(0); stt(0); __syncthreads();
  for (int it = 0; it < 32; ++it) {
    int cb = it & 1;
    const float* Ab = Asm + cb*(64*GAST);
    const float* Bb = Bsm + cb*(32*GBST);
    if (it < 31) ldt(it + 1);
    #pragma unroll
    for (int ks = 0; ks < 4; ++ks) {
      uint32_t a[2][4], bf[8][2];
      #pragma unroll
      for (int mt = 0; mt < 2; ++mt) {
        const float* ap = Ab + (wm*32 + mt*16 + gID)*GAST + ks*8;
        a[mt][0] = __float_as_uint(ap[tig]);
        a[mt][1] = __float_as_uint(ap[8*GAST + tig]);
        a[mt][2] = __float_as_uint(ap[tig + 4]);
        a[mt][3] = __float_as_uint(ap[8*GAST + tig + 4]);
      }
      #pragma unroll
      for (int nt = 0; nt < 8; ++nt) {
        int col = wn*64 + nt*8 + gID;
        bf[nt][0] = __float_as_uint(Bb[(ks*8 + tig)*GBST + col]);
        bf[nt][1] = __float_as_uint(Bb[(ks*8 + tig + 4)*GBST + col]);
      }
      #pragma unroll
      for (int mt = 0; mt < 2; ++mt)
        #pragma unroll
        for (int nt = 0; nt < 8; ++nt)
          mma8(c[mt*8+nt][0], c[mt*8+nt][1], c[mt*8+nt][2], c[mt*8+nt][3],
               a[mt][0], a[mt][1], a[mt][2], a[mt][3], bf[nt][0], bf[nt][1]);
    }
    if (it < 31) { stt(cb ^ 1); __syncthreads(); }
  }
  #pragma unroll
  for (int mt = 0; mt < 2; ++mt)
    #pragma unroll
    for (int nt = 0; nt < 8; ++nt) {
      int r0 = mBase + wm*32 + mt*16 + gID;
      int col = nBase + wn*64 + nt*8 + 2*tig;
      float* f = c[mt*8+nt];
      *(float2*)(C + (size_t)r0*N + col)     = make_float2(tf32f(f[0]*scale), tf32f(f[1]*scale));
      *(float2*)(C + (size_t)(r0+8)*N + col) = make_float2(tf32f(f[2]*scale), tf32f(f[3]*scale));
    }
}

// ---------------- fused differential flash attention -------------------------
// 256 threads = 8 warps: stream = wid&1, rowgrp = (wid>>1)&1, colgrp = wid>>2.
// Each warp: 16 rows x own 32 score-cols, PRIVATE online (m,l), FULL 128-col O.
// Column halves merge once at the end; streams combine via smem; single store.
__global__ __launch_bounds__(256, 1) void attn_tc(
    float* __restrict__ out,
    const float* __restrict__ lq1, const float* __restrict__ lk1,
    const float* __restrict__ lq2, const float* __restrict__ lk2) {
  extern __shared__ float sm[];
  float* Ks  = sm;                     // [db][stream][64][KSS]
  float* Vs  = Ks + 4*KS_TILE;         // [64][VSS]
  float* Ps  = Ks + PS_OFF;            // [8 warps][16][PSW]
  float* mbuf = Ks + ML_OFF;           // [8][16]
  float* lbuf = mbuf + 128;            // [8][16]
  float* lfin = lbuf + 128;            // [4][16]  (stream*2+rowgrp)

  int bid = blockIdx.x;
  int b, qt;
  if (bid < 148) { b = bid & 3; qt = (NQTA-1) - (bid >> 2); }
  else           { int r = bid - 148; b = r & 3; qt = r >> 2; }
  int q0 = qt * BQA;

  int tid = threadIdx.x, lane = tid & 31, wid = tid >> 5;
  int stream = wid & 1, rowgrp = (wid >> 1) & 1, colgrp = wid >> 2;
  int mrow = rowgrp*16, scol = colgrp*32;
  int gID = lane >> 2, tig = lane & 3;
  int kt_end = min((q0 + BQA) >> 6, (SEQ-1) >> 6);

  uint32_t KsU = (uint32_t)__cvta_generic_to_shared(Ks);
  uint32_t VsU = (uint32_t)__cvta_generic_to_shared(Vs);
  float* Pw = Ps + wid*16*PSW;

  auto issueK = [&](int ktile, int dbuf) {
    int j0 = ktile * BKA;
    #pragma unroll
    for (int i = 0; i < 16; ++i) {
      int idx = tid + i*256;
      int st  = idx >> 11;
      int rem = idx & 2047;
      int j = rem >> 5, d4 = rem & 31;
      const float* src = g_K + ((size_t)(b*SEQ + j0 + j))*QKN + st*HD + (d4 << 2);
      uint32_t dst = KsU + (((dbuf*2 + st)*KS_TILE) + j*KSS + (d4 << 2))*4u;
      cpa16(dst, src);
    }
  };
  auto issueV = [&](int ktile) {
    int j0 = ktile * BKA;
    #pragma unroll
    for (int i = 0; i < 8; ++i) {
      int idx = tid + i*256;
      int j = idx >> 5, d4 = idx & 31;
      const float* src = g_V + ((size_t)(b*SEQ + j0 + j))*HD + (d4 << 2);
      uint32_t dst = VsU + (j*VSS + (d4 << 2))*4u;
      cpa16(dst, src);
    }
  };

  // Q fragments (16 rows x this stream's 128 dims), kept in regs.
  uint32_t qf[16][4];
  {
    const float* qb = g_Q + ((size_t)(b*SEQ + q0 + mrow))*QKN + stream*HD;
    #pragma unroll
    for (int ks = 0; ks < 16; ++ks) {
      qf[ks][0] = __float_as_uint(qb[(size_t)gID*QKN     + ks*8 + tig]);
      qf[ks][1] = __float_as_uint(qb[(size_t)(gID+8)*QKN + ks*8 + tig]);
      qf[ks][2] = __float_as_uint(qb[(size_t)gID*QKN     + ks*8 + tig + 4]);
      qf[ks][3] = __float_as_uint(qb[(size_t)(gID+8)*QKN + ks*8 + tig + 4]);
    }
  }

  float O[16][4] = {};
  float m_lo = -1e30f, m_hi = -1e30f, l_lo = 0.f, l_hi = 0.f;

  issueK(0, 0); CP_COMMIT();

  for (int kt = 0; kt <= kt_end; ++kt) {
    int db = kt & 1;
    __syncthreads();                 // V/Ps/K(db^1) free
    issueV(kt); CP_COMMIT();
    bool more = (kt < kt_end);
    if (more) { issueK(kt + 1, db ^ 1); CP_COMMIT(); }
    if (more) asm volatile("cp.async.wait_group 1;" ::: "memory");
    else      asm volatile("cp.async.wait_group 0;" ::: "memory");
    __syncthreads();                 // K(kt)+V(kt) visible

    // scores over own 32 cols (Q pre-scaled)
    const float* Kb = Ks + (db*2 + stream)*KS_TILE;
    float S[4][4] = {};
    #pragma unroll
    for (int ks = 0; ks < 16; ++ks) {
      #pragma unroll
      for (int nt = 0; nt < 4; ++nt) {
        int jl = scol + nt*8 + gID;
        uint32_t b0 = __float_as_uint(Kb[jl*KSS + ks*8 + tig]);
        uint32_t b1 = __float_as_uint(Kb[jl*KSS + ks*8 + tig + 4]);
        mma8(S[nt][0], S[nt][1], S[nt][2], S[nt][3],
             qf[ks][0], qf[ks][1], qf[ks][2], qf[ks][3], b0, b1);
      }
    }

    // mask + warp-private row max over own slice
    int j0k = kt * BKA;
    int r_lo = q0 + mrow + gID, r_hi = r_lo + 8;
    float mx0 = -1e30f, mx1 = -1e30f;
    #pragma unroll
    for (int nt = 0; nt < 4; ++nt) {
      int jb = j0k + scol + nt*8 + 2*tig;
      S[nt][0] = (jb     <= r_lo + 1) ? S[nt][0] : -1e30f;
      S[nt][1] = (jb + 1 <= r_lo + 1) ? S[nt][1] : -1e30f;
      S[nt][2] = (jb     <= r_hi + 1) ? S[nt][2] : -1e30f;
      S[nt][3] = (jb + 1 <= r_hi + 1) ? S[nt][3] : -1e30f;
      mx0 = fmaxf(mx0, fmaxf(S[nt][0], S[nt][1]));
      mx1 = fmaxf(mx1, fmaxf(S[nt][2], S[nt][3]));
    }
    mx0 = fmaxf(mx0, __shfl_xor_sync(0xffffffffu, mx0, 1));
    mx0 = fmaxf(mx0, __shfl_xor_sync(0xffffffffu, mx0, 2));
    mx1 = fmaxf(mx1, __shfl_xor_sync(0xffffffffu, mx1, 1));
    mx1 = fmaxf(mx1, __shfl_xor_sync(0xffffffffu, mx1, 2));
    float mn0 = fmaxf(m_lo, mx0), mn1 = fmaxf(m_hi, mx1);
    float al0 = __expf(m_lo - mn0), al1 = __expf(m_hi - mn1);
    m_lo = mn0; m_hi = mn1;

    // p = valid ? exp(s-m) : 0  (predicate kills fully-masked-slice ghosts)
    float s0 = 0.f, s1 = 0.f;
    #pragma unroll
    for (int nt = 0; nt < 4; ++nt) {
      int jb = j0k + scol + nt*8 + 2*tig;
      float p00 = (jb     <= r_lo + 1) ? __expf(S[nt][0] - mn0) : 0.f;
      float p01 = (jb + 1 <= r_lo + 1) ? __expf(S[nt][1] - mn0) : 0.f;
      float p10 = (jb     <= r_hi + 1) ? __expf(S[nt][2] - mn1) : 0.f;
      float p11 = (jb + 1 <= r_hi + 1) ? __expf(S[nt][3] - mn1) : 0.f;
      s0 += p00 + p01; s1 += p10 + p11;
      *(float2*)(Pw + gID*PSW     + nt*8 + 2*tig) = make_float2(tf32f(p00), tf32f(p01));
      *(float2*)(Pw + (gID+8)*PSW + nt*8 + 2*tig) = make_float2(tf32f(p10), tf32f(p11));
    }
    s0 += __shfl_xor_sync(0xffffffffu, s0, 1); s0 += __shfl_xor_sync(0xffffffffu, s0, 2);
    s1 += __shfl_xor_sync(0xffffffffu, s1, 1); s1 += __shfl_xor_sync(0xffffffffu, s1, 2);
    l_lo = l_lo*al0 + s0;
    l_hi = l_hi*al1 + s1;
    #pragma unroll
    for (int nt = 0; nt < 16; ++nt) {
      O[nt][0] *= al0; O[nt][1] *= al0; O[nt][2] *= al1; O[nt][3] *= al1;
    }
    __syncwarp();                    // P visible within warp

    // O += P @ V  (own 32 k-rows, full 128 cols)
    #pragma unroll
    for (int kk = 0; kk < 4; ++kk) {
      uint32_t pa0 = __float_as_uint(Pw[gID*PSW     + kk*8 + tig]);
      uint32_t pa1 = __float_as_uint(Pw[(gID+8)*PSW + kk*8 + tig]);
      uint32_t pa2 = __float_as_uint(Pw[gID*PSW     + kk*8 + tig + 4]);
      uint32_t pa3 = __float_as_uint(Pw[(gID+8)*PSW + kk*8 + tig + 4]);
      #pragma unroll
      for (int nt = 0; nt < 16; ++nt) {
        int col = nt*8 + gID;
        uint32_t b0 = __float_as_uint(Vs[(scol + kk*8 + tig)*VSS + col]);
        uint32_t b1 = __float_as_uint(Vs[(scol + kk*8 + tig + 4)*VSS + col]);
        mma8(O[nt][0], O[nt][1], O[nt][2], O[nt][3], pa0, pa1, pa2, pa3, b0, b1);
      }
    }
  } // kt

  // ---- final combine: column halves, then streams ----
  if (tig == 0) {
    mbuf[wid*16 + gID] = m_lo;  mbuf[wid*16 + gID + 8] = m_hi;
    lbuf[wid*16 + gID] = l_lo;  lbuf[wid*16 + gID + 8] = l_hi;
  }
  __syncthreads();
  int peer = wid ^ 4;
  float pm_lo = mbuf[peer*16 + gID], pm_hi = mbuf[peer*16 + gID + 8];
  float pl_lo = lbuf[peer*16 + gID], pl_hi = lbuf[peer*16 + gID + 8];
  float mf_lo = fmaxf(m_lo, pm_lo),  mf_hi = fmaxf(m_hi, pm_hi);
  float af_lo = __expf(m_lo - mf_lo), af_hi = __expf(m_hi - mf_hi);
  float lf_lo = af_lo*l_lo + __expf(pm_lo - mf_lo)*pl_lo;
  float lf_hi = af_hi*l_hi + __expf(pm_hi - mf_hi)*pl_hi;
  if (colgrp == 0 && tig == 0) {
    lfin[(stream*2 + rowgrp)*16 + gID]     = lf_lo;
    lfin[(stream*2 + rowgrp)*16 + gID + 8] = lf_hi;
  }
  float* Ob = Ks + (stream*2 + rowgrp)*(16*OBS);   // reuse K smem
  if (colgrp == 0) {
    #pragma unroll
    for (int nt = 0; nt < 16; ++nt) {
      int col = nt*8 + 2*tig;
      *(float2*)(Ob + gID*OBS + col)     = make_float2(af_lo*O[nt][0], af_lo*O[nt][1]);
      *(float2*)(Ob + (gID+8)*OBS + col) = make_float2(af_hi*O[nt][2], af_hi*O[nt][3]);
    }
  }
  __syncthreads();
  if (colgrp == 1) {
    #pragma unroll
    for (int nt = 0; nt < 16; ++nt) {
      int col = nt*8 + 2*tig;
      float2* p0 = (float2*)(Ob + gID*OBS + col);
      float2* p1 = (float2*)(Ob + (gID+8)*OBS + col);
      float2 t0 = *p0, t1 = *p1;
      t0.x += af_lo*O[nt][0]; t0.y += af_lo*O[nt][1];
      t1.x += af_hi*O[nt][2]; t1.y += af_hi*O[nt][3];
      *p0 = t0; *p1 = t1;
    }
  }
  __syncthreads();
  if (stream == 0) {
    // lambda (redundant per store-warp: 4 elems/lane + shuffle reduce)
    float d1 = 0.f, d2 = 0.f;
    #pragma unroll
    for (int i = 0; i < 4; ++i) {
      int ix = lane + i*32;
      d1 += lq1[ix]*lk1[ix];
      d2 += lq2[ix]*lk2[ix];
    }
    #pragma unroll
    for (int off = 16; off; off >>= 1) {
      d1 += __shfl_xor_sync(0xffffffffu, d1, off);
      d2 += __shfl_xor_sync(0xffffffffu, d2, off);
    }
    float lbd = __expf(d1) - __expf(d2) + 0.8f;

    const float* Ob0 = Ks + (0*2 + rowgrp)*(16*OBS);
    const float* Ob1 = Ks + (1*2 + rowgrp)*(16*OBS);
    const float* lf0 = lfin + (0*2 + rowgrp)*16;
    const float* lf1 = lfin + (1*2 + rowgrp)*16;
    for (int idx = lane; idx < 16*64; idx += 32) {
      int r = idx >> 6, cc = (idx & 63) + colgrp*64;
      float o = Ob0[r*OBS + cc] / lf0[r] - lbd * (Ob1[r*OBS + cc] / lf1[r]);
      out[((size_t)(b*SEQ + q0 + mrow + r))*HD + cc] = o;
    }
  }
}

// ---------------- launch ------------------------------------------------------
extern "C" void kernel_launch(void* const* d_in, const int* in_sizes, int n_in,
                              void* d_out, int out_size) {
  const float* q   = (const float*)d_in[0];
  const float* k   = (const float*)d_in[1];
  const float* v   = (const float*)d_in[2];
  const float* Wq  = (const float*)d_in[3];
  const float* Wk  = (const float*)d_in[4];
  const float* Wv  = (const float*)d_in[5];
  const float* lq1 = (const float*)d_in[6];
  const float* lk1 = (const float*)d_in[7];
  const float* lq2 = (const float*)d_in[8];
  const float* lk2 = (const float*)d_in[9];
  float* out = (float*)d_out;

  cudaFuncSetAttribute(gemm_all, cudaFuncAttributeMaxDynamicSharedMemorySize, GEMM_SMEM);
  cudaFuncSetAttribute(attn_tc, cudaFuncAttributeMaxDynamicSharedMemorySize, ATT_SMEM);

  gemm_all<<<640, 128, GEMM_SMEM>>>(q, k, v, Wq, Wk, Wv);
  attn_tc<<<4*NQTA, 256, ATT_SMEM>>>(out, lq1, lk1, lq2, lk2);
}